// round 1
// baseline (speedup 1.0000x reference)
#include <cuda_runtime.h>
#include <cstdint>

// Problem constants (fixed by the dataset)
#define BB 4096
#define NN 16384
#define FF 16384
#define THREADS 1024
#define PER_THREAD (NN / THREADS)   // 16 neurons per thread
#define MEAN_SUB 0.1f

__global__ __launch_bounds__(THREADS, 1)
void sensory_cortex_kernel(const float* __restrict__ enc,
                           const float* __restrict__ w,
                           const int*   __restrict__ pref,
                           float* __restrict__ out) {
    extern __shared__ float srow[];   // FF floats = 64 KiB
    const int t = threadIdx.x;
    const int b = blockIdx.x;

    // ---- Stage the enc row into shared memory (coalesced float4) ----
    {
        const float4* enc4 = reinterpret_cast<const float4*>(enc + (size_t)b * FF);
        float4* s4 = reinterpret_cast<float4*>(srow);
        #pragma unroll
        for (int i = 0; i < FF / 4 / THREADS; i++) {   // 4 iterations
            s4[t + i * THREADS] = enc4[t + i * THREADS];
        }
    }
    __syncthreads();

    // ---- Gather + scale, accumulate local sum ----
    // Each thread owns PER_THREAD/4 = 4 groups of 4 consecutive neurons:
    // n = t*4 + g*4096 .. +3  -> vectorized int4/float4 loads & stores.
    float spec[PER_THREAD];
    float lsum = 0.0f;
    #pragma unroll
    for (int g = 0; g < PER_THREAD / 4; g++) {        // 4 groups
        const int n0 = t * 4 + g * (THREADS * 4);
        int4   p4 = *reinterpret_cast<const int4*>(pref + n0);
        float4 w4 = *reinterpret_cast<const float4*>(w + n0);
        float v0 = srow[p4.x & (FF - 1)] * w4.x;
        float v1 = srow[p4.y & (FF - 1)] * w4.y;
        float v2 = srow[p4.z & (FF - 1)] * w4.z;
        float v3 = srow[p4.w & (FF - 1)] * w4.w;
        spec[g * 4 + 0] = v0;
        spec[g * 4 + 1] = v1;
        spec[g * 4 + 2] = v2;
        spec[g * 4 + 3] = v3;
        lsum += (v0 + v1) + (v2 + v3);
    }

    // ---- Block reduction of lsum (warp shuffle + smem, reuse srow) ----
    #pragma unroll
    for (int o = 16; o > 0; o >>= 1)
        lsum += __shfl_xor_sync(0xFFFFFFFFu, lsum, o);

    __syncthreads();   // everyone is done gathering from srow; safe to reuse
    if ((t & 31) == 0) srow[t >> 5] = lsum;   // 32 warp sums
    __syncthreads();

    float total;
    {
        // every thread reads the 32 partials (broadcast-ish, cheap)
        float s = srow[t & 31];
        #pragma unroll
        for (int o = 16; o > 0; o >>= 1)
            s += __shfl_xor_sync(0xFFFFFFFFu, s, o);
        total = s;
    }

    const float sub = MEAN_SUB * (total * (1.0f / (float)NN));

    // ---- Write output ----
    float* orow = out + (size_t)b * NN;
    #pragma unroll
    for (int g = 0; g < PER_THREAD / 4; g++) {
        const int n0 = t * 4 + g * (THREADS * 4);
        float4 o4;
        o4.x = fmaxf(spec[g * 4 + 0] - sub, 0.0f);
        o4.y = fmaxf(spec[g * 4 + 1] - sub, 0.0f);
        o4.z = fmaxf(spec[g * 4 + 2] - sub, 0.0f);
        o4.w = fmaxf(spec[g * 4 + 3] - sub, 0.0f);
        *reinterpret_cast<float4*>(orow + n0) = o4;
    }
}

extern "C" void kernel_launch(void* const* d_in, const int* in_sizes, int n_in,
                              void* d_out, int out_size) {
    const float* enc  = (const float*)d_in[0];   // [B, F] float32
    const float* w    = (const float*)d_in[1];   // [N]    float32
    const int*   pref = (const int*)d_in[2];     // [N]    int32
    float* out = (float*)d_out;                  // [B, N] float32

    static bool attr_set = false;
    if (!attr_set) {
        cudaFuncSetAttribute(sensory_cortex_kernel,
                             cudaFuncAttributeMaxDynamicSharedMemorySize,
                             FF * sizeof(float));
        attr_set = true;
    }

    sensory_cortex_kernel<<<BB, THREADS, FF * sizeof(float)>>>(enc, w, pref, out);
}

// round 2
// speedup vs baseline: 1.3031x; 1.3031x over previous
#include <cuda_runtime.h>
#include <cstdint>

// Problem constants (fixed by the dataset)
#define BB 4096
#define NN 16384
#define FF 16384
#define THREADS 1024
#define GRID 152                 // one persistent CTA per GB300 SM
#define NBUF 3
#define BUF_BYTES (FF * 4)       // 64 KiB per row buffer
#define MEAN_SUB 0.1f

// smem layout
#define SMEM_BUFS    0
#define SMEM_SCRATCH (NBUF * BUF_BYTES)            // 196608: 2 x 32 floats
#define SMEM_MBAR    (SMEM_SCRATCH + 2 * 32 * 4)   // 196864: 3 x 8B mbarriers
#define SMEM_TOTAL   (SMEM_MBAR + NBUF * 8 + 8)

__device__ __forceinline__ uint32_t smem_u32(const void* p) {
    uint32_t a;
    asm("{ .reg .u64 t; cvta.to.shared.u64 t, %1; cvt.u32.u64 %0, t; }"
        : "=r"(a) : "l"(p));
    return a;
}

__device__ __forceinline__ void mbar_wait_parity(uint32_t mb, uint32_t ph) {
    uint32_t done;
    asm volatile(
        "{\n\t.reg .pred p;\n\t"
        "mbarrier.try_wait.parity.acquire.cta.shared::cta.b64 p, [%1], %2;\n\t"
        "selp.b32 %0, 1, 0, p;\n\t}"
        : "=r"(done) : "r"(mb), "r"(ph) : "memory");
    if (!done) {
        asm volatile(
            "{\n\t.reg .pred P1;\n\t"
            "WL_%=:\n\t"
            "mbarrier.try_wait.parity.acquire.cta.shared::cta.b64 P1, [%0], %1, 0x989680;\n\t"
            "@P1 bra.uni WD_%=;\n\t"
            "bra.uni WL_%=;\n\t"
            "WD_%=:\n\t}"
            :: "r"(mb), "r"(ph) : "memory");
    }
}

__device__ __forceinline__ void issue_row_load(uint32_t dst_smem, const float* src,
                                               uint32_t mb) {
    asm volatile("mbarrier.arrive.expect_tx.shared.b64 _, [%0], %1;"
                 :: "r"(mb), "r"((uint32_t)BUF_BYTES) : "memory");
    asm volatile("cp.async.bulk.shared::cta.global.mbarrier::complete_tx::bytes "
                 "[%0], [%1], %2, [%3];"
                 :: "r"(dst_smem), "l"(src), "r"((uint32_t)BUF_BYTES), "r"(mb)
                 : "memory");
}

__global__ __launch_bounds__(THREADS, 1)
void sensory_pipe_kernel(const float* __restrict__ enc,
                         const float* __restrict__ w,
                         const int*   __restrict__ pref,
                         float* __restrict__ out) {
    extern __shared__ char smem[];
    float* bufs    = reinterpret_cast<float*>(smem + SMEM_BUFS);
    float* scratch = reinterpret_cast<float*>(smem + SMEM_SCRATCH);
    const uint32_t bufs_u32 = smem_u32(smem + SMEM_BUFS);
    const uint32_t mbar     = smem_u32(smem + SMEM_MBAR);

    const int t   = threadIdx.x;
    const int bid = blockIdx.x;

    if (t == 0) {
        #pragma unroll
        for (int s = 0; s < NBUF; s++)
            asm volatile("mbarrier.init.shared.b64 [%0], 1;"
                         :: "r"(mbar + s * 8) : "memory");
    }
    __syncthreads();

    // Prologue: prefetch first NBUF rows
    if (t == 0) {
        #pragma unroll
        for (int j = 0; j < NBUF; j++) {
            int r = bid + j * GRID;
            if (r < BB)
                issue_row_load(bufs_u32 + j * BUF_BYTES,
                               enc + (size_t)r * FF, mbar + j * 8);
        }
    }

    int s = 0;          // ring slot
    uint32_t ph = 0;    // parity for current slot wait
    int wrap = 0;       // counts slots until phase flip

    for (int i = 0, r = bid; r < BB; i++, r += GRID) {
        // ---- wait for this row's buffer ----
        mbar_wait_parity(mbar + s * 8, ph);
        const float* srow = bufs + s * FF;

        // ---- gather + scale + local sum ----
        float spec[16];
        float lsum = 0.0f;
        #pragma unroll
        for (int g = 0; g < 4; g++) {
            const int n0 = t * 4 + g * (THREADS * 4);
            int4   p4 = *reinterpret_cast<const int4*>(pref + n0);
            float4 w4 = *reinterpret_cast<const float4*>(w + n0);
            float v0 = srow[p4.x & (FF - 1)] * w4.x;
            float v1 = srow[p4.y & (FF - 1)] * w4.y;
            float v2 = srow[p4.z & (FF - 1)] * w4.z;
            float v3 = srow[p4.w & (FF - 1)] * w4.w;
            spec[g * 4 + 0] = v0;
            spec[g * 4 + 1] = v1;
            spec[g * 4 + 2] = v2;
            spec[g * 4 + 3] = v3;
            lsum += (v0 + v1) + (v2 + v3);
        }

        // ---- reduction: warp shuffle -> scratch (double buffered) ----
        #pragma unroll
        for (int o = 16; o > 0; o >>= 1)
            lsum += __shfl_xor_sync(0xFFFFFFFFu, lsum, o);
        float* sc = scratch + (i & 1) * 32;
        if ((t & 31) == 0) sc[t >> 5] = lsum;
        __syncthreads();   // all gathers from buf[s] done; scratch written

        // ---- recycle buffer slot: prefetch row r + 3*GRID ----
        if (t == 0) {
            int r3 = r + NBUF * GRID;
            if (r3 < BB)
                issue_row_load(bufs_u32 + s * BUF_BYTES,
                               enc + (size_t)r3 * FF, mbar + s * 8);
        }

        // ---- finish reduction ----
        float v = sc[t & 31];
        #pragma unroll
        for (int o = 16; o > 0; o >>= 1)
            v += __shfl_xor_sync(0xFFFFFFFFu, v, o);
        const float sub = MEAN_SUB * (v * (1.0f / (float)NN));

        // ---- write output ----
        float* orow = out + (size_t)r * NN;
        #pragma unroll
        for (int g = 0; g < 4; g++) {
            const int n0 = t * 4 + g * (THREADS * 4);
            float4 o4;
            o4.x = fmaxf(spec[g * 4 + 0] - sub, 0.0f);
            o4.y = fmaxf(spec[g * 4 + 1] - sub, 0.0f);
            o4.z = fmaxf(spec[g * 4 + 2] - sub, 0.0f);
            o4.w = fmaxf(spec[g * 4 + 3] - sub, 0.0f);
            *reinterpret_cast<float4*>(orow + n0) = o4;
        }

        // ---- advance ring ----
        s++;
        if (s == NBUF) { s = 0; ph ^= 1; }
        (void)wrap;
    }
}

extern "C" void kernel_launch(void* const* d_in, const int* in_sizes, int n_in,
                              void* d_out, int out_size) {
    const float* enc  = (const float*)d_in[0];   // [B, F] float32
    const float* w    = (const float*)d_in[1];   // [N]    float32
    const int*   pref = (const int*)d_in[2];     // [N]    int32
    float* out = (float*)d_out;                  // [B, N] float32

    static bool attr_set = false;
    if (!attr_set) {
        cudaFuncSetAttribute(sensory_pipe_kernel,
                             cudaFuncAttributeMaxDynamicSharedMemorySize,
                             SMEM_TOTAL);
        attr_set = true;
    }

    sensory_pipe_kernel<<<GRID, THREADS, SMEM_TOTAL>>>(enc, w, pref, out);
}